// round 10
// baseline (speedup 1.0000x reference)
#include <cuda_runtime.h>
#include <math.h>

// ---------------------------------------------------------------------------
// Fully fused kernel. The circuit factorizes: all entangling gates stay within
// wire pairs {0,1} and {2,3}, so U = U_A (x) U_B and each PauliZ expectation
// is a 9-term bilinear form over (1, cos d, sin d) of two angles.
//
// Per block (one image):
//   - all threads issue their x loads first (hide DRAM latency)
//   - warp 0 alone computes the theta-dependent 9-term coefficients
//     (3 stages, __syncwarp only -- other warps never wait on prep)
//   - ONE __syncthreads, then each thread t<196 evaluates its patch and
//     immediately computes its partial GEMV contribution from registers
//     (no feats smem round-trip), 10x LDG.128 of W
//   - block reduction + log_softmax
// ---------------------------------------------------------------------------

__device__ __forceinline__ void ap1(float* vr, float* vi, int m,
    float g00r, float g00i, float g01r, float g01i,
    float g10r, float g10i, float g11r, float g11i)
{
    #pragma unroll
    for (int z = 0; z < 4; z++) {
        if (z & m) continue;
        int z1 = z | m;
        float ar = vr[z],  ai = vi[z];
        float br = vr[z1], bi = vi[z1];
        vr[z]  = g00r*ar - g00i*ai + g01r*br - g01i*bi;
        vi[z]  = g00r*ai + g00i*ar + g01r*bi + g01i*br;
        vr[z1] = g10r*ar - g10i*ai + g11r*br - g11i*bi;
        vi[z1] = g10r*ai + g10i*ar + g11r*bi + g11i*br;
    }
}

__global__ __launch_bounds__(256)
void fused_kernel(const float* __restrict__ x,
                  const float* __restrict__ cw,
                  const float* __restrict__ theta,
                  const float* __restrict__ W,
                  const float* __restrict__ bvec,
                  float* __restrict__ out)
{
    __shared__ float Ur[2][4][4], Ui[2][4][4];     // [pair][z][col]
    __shared__ float M[2][2][4][4];                // [pair][q][i][j]
    __shared__ float2 scA[9], scB[9];              // 9-term coeffs per pair
    __shared__ float wpart[8][10];
    __shared__ float slog[10];
    __shared__ float slse;

    int t = threadIdx.x;
    int b = blockIdx.x;

    // ---- Step 0: issue x loads immediately (before any dependency) ----
    float4 r0a, r0b, r1a, r1b;
    if (t < 196) {
        int r  = t / 7;
        int c4 = t % 7;
        const float* px = x + (size_t)b * 3136 + (2 * r) * 56 + 8 * c4;
        r0a = *(const float4*)(px);
        r0b = *(const float4*)(px + 4);
        r1a = *(const float4*)(px + 56);
        r1b = *(const float4*)(px + 60);
    }
    float w00 = cw[0], w01 = cw[1], w10 = cw[2], w11 = cw[3];

    // ---- Prep: warp 0 only, __syncwarp between stages ----
    if (t < 32) {
        if (t < 8) {
            int pair = t >> 2;
            int col  = t & 3;
            float vr[4] = {0.f, 0.f, 0.f, 0.f};
            float vi[4] = {0.f, 0.f, 0.f, 0.f};
            vr[col] = 1.f;
            if (pair == 0) {
                // Ry(th0) w0, Rx(th1) w1, CNOT(0,1), Rx(th4) w0
                { float c = cosf(0.5f*theta[0]), s = sinf(0.5f*theta[0]);
                  ap1(vr, vi, 2,  c,0.f, -s,0.f,  s,0.f,  c,0.f); }
                { float c = cosf(0.5f*theta[1]), s = sinf(0.5f*theta[1]);
                  ap1(vr, vi, 1,  c,0.f, 0.f,-s, 0.f,-s,  c,0.f); }
                { float tr = vr[2], ti = vi[2];
                  vr[2] = vr[3]; vi[2] = vi[3]; vr[3] = tr; vi[3] = ti; }
                { float c = cosf(0.5f*theta[4]), s = sinf(0.5f*theta[4]);
                  ap1(vr, vi, 2,  c,0.f, 0.f,-s, 0.f,-s,  c,0.f); }
            } else {
                // Rz(th2) w2, Ry(th3) w3, CNOT(2,3), Rz(th5) w3
                { float c = cosf(0.5f*theta[2]), s = sinf(0.5f*theta[2]);
                  ap1(vr, vi, 2,  c,-s, 0.f,0.f, 0.f,0.f,  c,s); }
                { float c = cosf(0.5f*theta[3]), s = sinf(0.5f*theta[3]);
                  ap1(vr, vi, 1,  c,0.f, -s,0.f,  s,0.f,  c,0.f); }
                { float tr = vr[2], ti = vi[2];
                  vr[2] = vr[3]; vi[2] = vi[3]; vr[3] = tr; vi[3] = ti; }
                { float c = cosf(0.5f*theta[5]), s = sinf(0.5f*theta[5]);
                  ap1(vr, vi, 1,  c,-s, 0.f,0.f, 0.f,0.f,  c,s); }
            }
            #pragma unroll
            for (int z = 0; z < 4; z++) { Ur[pair][z][col] = vr[z]; Ui[pair][z][col] = vi[z]; }
        }
        __syncwarp();
        {
            int pair = t >> 4;
            int i = (t >> 2) & 3, j = t & 3;
            float a0 = 0.f, a1 = 0.f;
            #pragma unroll
            for (int z = 0; z < 4; z++) {
                float re = Ur[pair][z][i]*Ur[pair][z][j] + Ui[pair][z][i]*Ui[pair][z][j];
                a0 += (z & 2) ? -re : re;
                a1 += (z & 1) ? -re : re;
            }
            M[pair][0][i][j] = a0;
            M[pair][1][i][j] = a1;
        }
        __syncwarp();
        if (t < 18) {
            int pair = (t >= 9) ? 1 : 0;
            int e = pair ? (t - 9) : t;
            int e0 = e / 3, e1 = e % 3;
            float c0 = 0.f, c1 = 0.f;
            #pragma unroll
            for (int s = 0; s < 4; s++) {
                int i = 0, j = 0; float sg = 1.f;
                { int bsel = s & 1; int iw, jw; float ss;
                  if (e0 == 0)      { iw = bsel; jw = bsel;     ss = 1.f; }
                  else if (e0 == 1) { iw = bsel; jw = bsel;     ss = bsel ? -1.f : 1.f; }
                  else              { iw = bsel; jw = 1 - bsel; ss = 1.f; }
                  i |= iw << 1; j |= jw << 1; sg *= ss; }
                { int bsel = (s >> 1) & 1; int iw, jw; float ss;
                  if (e1 == 0)      { iw = bsel; jw = bsel;     ss = 1.f; }
                  else if (e1 == 1) { iw = bsel; jw = bsel;     ss = bsel ? -1.f : 1.f; }
                  else              { iw = bsel; jw = 1 - bsel; ss = 1.f; }
                  i |= iw; j |= jw; sg *= ss; }
                c0 += sg * M[pair][0][i][j];
                c1 += sg * M[pair][1][i][j];
            }
            float2 v = make_float2(0.25f * c0, 0.25f * c1);
            if (pair == 0) scA[e] = v; else scB[e] = v;
        }
    }

    // ---- Conv + sincos (independent of prep; runs before the sync) ----
    float fa1 = 1.f, fa2 = 0.f, fb1 = 1.f, fb2 = 0.f;
    float fc1 = 1.f, fc2 = 0.f, fd1 = 1.f, fd2 = 0.f;
    if (t < 196) {
        float d0 = w00*r0a.x + w01*r0a.y + w10*r1a.x + w11*r1a.y;
        float d1 = w00*r0a.z + w01*r0a.w + w10*r1a.z + w11*r1a.w;
        float d2 = w00*r0b.x + w01*r0b.y + w10*r1b.x + w11*r1b.y;
        float d3 = w00*r0b.z + w01*r0b.w + w10*r1b.z + w11*r1b.w;
        __sincosf(d0, &fa2, &fa1);
        __sincosf(d1, &fb2, &fb1);
        __sincosf(d2, &fc2, &fc1);
        __sincosf(d3, &fd2, &fd1);
    }
    __syncthreads();   // coefficients ready

    // ---- Patch eval (registers) + immediate partial GEMV ----
    float acc[10];
    #pragma unroll
    for (int k = 0; k < 10; k++) acc[k] = 0.f;

    if (t < 196) {
        float fa[3] = {1.f, fa1, fa2};
        float fb[3] = {1.f, fb1, fb2};
        float fc[3] = {1.f, fc1, fc2};
        float fd[3] = {1.f, fd1, fd2};

        float m0 = 0.f, m1 = 0.f, m2 = 0.f, m3 = 0.f;
        int idx = 0;
        #pragma unroll
        for (int e0 = 0; e0 < 3; e0++) {
            #pragma unroll
            for (int e1 = 0; e1 < 3; e1++) {
                float pA = fa[e0] * fb[e1];
                float pB = fc[e0] * fd[e1];
                float2 kA = scA[idx];
                float2 kB = scB[idx];
                idx++;
                m0 = fmaf(kA.x, pA, m0);
                m1 = fmaf(kA.y, pA, m1);
                m2 = fmaf(kB.x, pB, m2);
                m3 = fmaf(kB.y, pB, m3);
            }
        }

        // partial GEMV: this thread owns features [4t, 4t+4)
        #pragma unroll
        for (int k = 0; k < 10; k++) {
            float4 w4 = __ldg((const float4*)(W + k * 784 + 4 * t));
            acc[k] = fmaf(m0, w4.x, fmaf(m1, w4.y, fmaf(m2, w4.z, m3 * w4.w)));
        }
    }

    // ---- Block reduction of acc[10] ----
    // Warps 6/7 have partially/fully inactive patch lanes; their acc is 0, so
    // summing all 8 warp partials below is correct.
    #pragma unroll
    for (int k = 0; k < 10; k++) {
        float v = acc[k];
        v += __shfl_xor_sync(0xffffffffu, v, 16);
        v += __shfl_xor_sync(0xffffffffu, v, 8);
        v += __shfl_xor_sync(0xffffffffu, v, 4);
        v += __shfl_xor_sync(0xffffffffu, v, 2);
        v += __shfl_xor_sync(0xffffffffu, v, 1);
        acc[k] = v;
    }
    int lane = t & 31, wid = t >> 5;
    if (lane == 0) {
        #pragma unroll
        for (int k = 0; k < 10; k++) wpart[wid][k] = acc[k];
    }
    __syncthreads();

    // ---- Final logits + log_softmax (warp 0 only) ----
    if (t < 32) {
        if (t < 10) {
            float v = bvec[t];
            #pragma unroll
            for (int w = 0; w < 8; w++) v += wpart[w][t];
            slog[t] = v;
        }
        __syncwarp();
        if (t == 0) {
            float mx = slog[0];
            #pragma unroll
            for (int k = 1; k < 10; k++) mx = fmaxf(mx, slog[k]);
            float se = 0.f;
            #pragma unroll
            for (int k = 0; k < 10; k++) se += __expf(slog[k] - mx);
            slse = mx + __logf(se);
        }
        __syncwarp();
        if (t < 10) out[(size_t)b * 10 + t] = slog[t] - slse;
    }
}

// ---------------------------------------------------------------------------

extern "C" void kernel_launch(void* const* d_in, const int* in_sizes, int n_in,
                              void* d_out, int out_size)
{
    const float* x     = (const float*)d_in[0];   // [2048,1,56,56]
    const float* cw    = (const float*)d_in[1];   // [1,1,2,2]
    const float* theta = (const float*)d_in[2];   // [6]
    const float* W     = (const float*)d_in[3];   // [10,784]
    const float* bvec  = (const float*)d_in[4];   // [10]
    float* out = (float*)d_out;                   // [2048,10]

    int B = in_sizes[0] / 3136;                   // 2048

    fused_kernel<<<B, 256>>>(x, cw, theta, W, bvec, out);
}

// round 11
// speedup vs baseline: 1.2048x; 1.2048x over previous
#include <cuda_runtime.h>
#include <math.h>

// ---------------------------------------------------------------------------
// Fully fused kernel, 2 images per block. The circuit factorizes into wire
// pairs {0,1} and {2,3}: U = U_A (x) U_B, and each PauliZ expectation is a
// 9-term bilinear form over (1, cos d, sin d) of two angles.
//
// Per block (two images, 224 threads = 7 warps):
//   - threads t<196 issue 8 x-loads (patch t of image A and image B) first
//   - warp 0 computes the theta-dependent 9-term coefficients (syncwarp only)
//   - ONE __syncthreads, then each thread evaluates BOTH patches and folds
//     them into two register GEMV partials; each W float4 is loaded once and
//     used for both images (halves chip-wide W traffic)
//   - dual block reduction + dual log_softmax
// ---------------------------------------------------------------------------

__device__ __forceinline__ void ap1(float* vr, float* vi, int m,
    float g00r, float g00i, float g01r, float g01i,
    float g10r, float g10i, float g11r, float g11i)
{
    #pragma unroll
    for (int z = 0; z < 4; z++) {
        if (z & m) continue;
        int z1 = z | m;
        float ar = vr[z],  ai = vi[z];
        float br = vr[z1], bi = vi[z1];
        vr[z]  = g00r*ar - g00i*ai + g01r*br - g01i*bi;
        vi[z]  = g00r*ai + g00i*ar + g01r*bi + g01i*br;
        vr[z1] = g10r*ar - g10i*ai + g11r*br - g11i*bi;
        vi[z1] = g10r*ai + g10i*ar + g11r*bi + g11i*br;
    }
}

__global__ __launch_bounds__(224)
void fused_kernel(const float* __restrict__ x,
                  const float* __restrict__ cw,
                  const float* __restrict__ theta,
                  const float* __restrict__ W,
                  const float* __restrict__ bvec,
                  float* __restrict__ out)
{
    __shared__ float Ur[2][4][4], Ui[2][4][4];     // [pair][z][col]
    __shared__ float M[2][2][4][4];                // [pair][q][i][j]
    __shared__ float2 scA[9], scB[9];              // 9-term coeffs per pair
    __shared__ float wpart[2][7][10];              // [img][warp][k]
    __shared__ float slog[2][10];
    __shared__ float slse[2];

    int t = threadIdx.x;
    int b = blockIdx.x;                            // images 2b, 2b+1

    // ---- Step 0: issue all x loads immediately (8 LDG.128 in flight) ----
    float4 a0a, a0b, a1a, a1b;                     // image A
    float4 b0a, b0b, b1a, b1b;                     // image B
    if (t < 196) {
        int r  = t / 7;
        int c4 = t % 7;
        size_t off = (2 * r) * 56 + 8 * c4;
        const float* pxA = x + (size_t)(2 * b)     * 3136 + off;
        const float* pxB = x + (size_t)(2 * b + 1) * 3136 + off;
        a0a = *(const float4*)(pxA);
        a0b = *(const float4*)(pxA + 4);
        a1a = *(const float4*)(pxA + 56);
        a1b = *(const float4*)(pxA + 60);
        b0a = *(const float4*)(pxB);
        b0b = *(const float4*)(pxB + 4);
        b1a = *(const float4*)(pxB + 56);
        b1b = *(const float4*)(pxB + 60);
    }
    float w00 = cw[0], w01 = cw[1], w10 = cw[2], w11 = cw[3];

    // ---- Prep: warp 0 only, __syncwarp between stages ----
    if (t < 32) {
        if (t < 8) {
            int pair = t >> 2;
            int col  = t & 3;
            float vr[4] = {0.f, 0.f, 0.f, 0.f};
            float vi[4] = {0.f, 0.f, 0.f, 0.f};
            vr[col] = 1.f;
            if (pair == 0) {
                // Ry(th0) w0, Rx(th1) w1, CNOT(0,1), Rx(th4) w0
                { float c = cosf(0.5f*theta[0]), s = sinf(0.5f*theta[0]);
                  ap1(vr, vi, 2,  c,0.f, -s,0.f,  s,0.f,  c,0.f); }
                { float c = cosf(0.5f*theta[1]), s = sinf(0.5f*theta[1]);
                  ap1(vr, vi, 1,  c,0.f, 0.f,-s, 0.f,-s,  c,0.f); }
                { float tr = vr[2], ti = vi[2];
                  vr[2] = vr[3]; vi[2] = vi[3]; vr[3] = tr; vi[3] = ti; }
                { float c = cosf(0.5f*theta[4]), s = sinf(0.5f*theta[4]);
                  ap1(vr, vi, 2,  c,0.f, 0.f,-s, 0.f,-s,  c,0.f); }
            } else {
                // Rz(th2) w2, Ry(th3) w3, CNOT(2,3), Rz(th5) w3
                { float c = cosf(0.5f*theta[2]), s = sinf(0.5f*theta[2]);
                  ap1(vr, vi, 2,  c,-s, 0.f,0.f, 0.f,0.f,  c,s); }
                { float c = cosf(0.5f*theta[3]), s = sinf(0.5f*theta[3]);
                  ap1(vr, vi, 1,  c,0.f, -s,0.f,  s,0.f,  c,0.f); }
                { float tr = vr[2], ti = vi[2];
                  vr[2] = vr[3]; vi[2] = vi[3]; vr[3] = tr; vi[3] = ti; }
                { float c = cosf(0.5f*theta[5]), s = sinf(0.5f*theta[5]);
                  ap1(vr, vi, 1,  c,-s, 0.f,0.f, 0.f,0.f,  c,s); }
            }
            #pragma unroll
            for (int z = 0; z < 4; z++) { Ur[pair][z][col] = vr[z]; Ui[pair][z][col] = vi[z]; }
        }
        __syncwarp();
        {
            int pair = t >> 4;
            int i = (t >> 2) & 3, j = t & 3;
            float p0 = 0.f, p1 = 0.f;
            #pragma unroll
            for (int z = 0; z < 4; z++) {
                float re = Ur[pair][z][i]*Ur[pair][z][j] + Ui[pair][z][i]*Ui[pair][z][j];
                p0 += (z & 2) ? -re : re;
                p1 += (z & 1) ? -re : re;
            }
            M[pair][0][i][j] = p0;
            M[pair][1][i][j] = p1;
        }
        __syncwarp();
        if (t < 18) {
            int pair = (t >= 9) ? 1 : 0;
            int e = pair ? (t - 9) : t;
            int e0 = e / 3, e1 = e % 3;
            float c0 = 0.f, c1 = 0.f;
            #pragma unroll
            for (int s = 0; s < 4; s++) {
                int i = 0, j = 0; float sg = 1.f;
                { int bsel = s & 1; int iw, jw; float ss;
                  if (e0 == 0)      { iw = bsel; jw = bsel;     ss = 1.f; }
                  else if (e0 == 1) { iw = bsel; jw = bsel;     ss = bsel ? -1.f : 1.f; }
                  else              { iw = bsel; jw = 1 - bsel; ss = 1.f; }
                  i |= iw << 1; j |= jw << 1; sg *= ss; }
                { int bsel = (s >> 1) & 1; int iw, jw; float ss;
                  if (e1 == 0)      { iw = bsel; jw = bsel;     ss = 1.f; }
                  else if (e1 == 1) { iw = bsel; jw = bsel;     ss = bsel ? -1.f : 1.f; }
                  else              { iw = bsel; jw = 1 - bsel; ss = 1.f; }
                  i |= iw; j |= jw; sg *= ss; }
                c0 += sg * M[pair][0][i][j];
                c1 += sg * M[pair][1][i][j];
            }
            float2 v = make_float2(0.25f * c0, 0.25f * c1);
            if (pair == 0) scA[e] = v; else scB[e] = v;
        }
    }

    // ---- Conv + sincos for both images (independent of prep) ----
    float Aa1 = 1.f, Aa2 = 0.f, Ab1 = 1.f, Ab2 = 0.f;
    float Ac1 = 1.f, Ac2 = 0.f, Ad1 = 1.f, Ad2 = 0.f;
    float Ba1 = 1.f, Ba2 = 0.f, Bb1 = 1.f, Bb2 = 0.f;
    float Bc1 = 1.f, Bc2 = 0.f, Bd1 = 1.f, Bd2 = 0.f;
    if (t < 196) {
        float d0 = w00*a0a.x + w01*a0a.y + w10*a1a.x + w11*a1a.y;
        float d1 = w00*a0a.z + w01*a0a.w + w10*a1a.z + w11*a1a.w;
        float d2 = w00*a0b.x + w01*a0b.y + w10*a1b.x + w11*a1b.y;
        float d3 = w00*a0b.z + w01*a0b.w + w10*a1b.z + w11*a1b.w;
        __sincosf(d0, &Aa2, &Aa1);
        __sincosf(d1, &Ab2, &Ab1);
        __sincosf(d2, &Ac2, &Ac1);
        __sincosf(d3, &Ad2, &Ad1);
        float e0 = w00*b0a.x + w01*b0a.y + w10*b1a.x + w11*b1a.y;
        float e1 = w00*b0a.z + w01*b0a.w + w10*b1a.z + w11*b1a.w;
        float e2 = w00*b0b.x + w01*b0b.y + w10*b1b.x + w11*b1b.y;
        float e3 = w00*b0b.z + w01*b0b.w + w10*b1b.z + w11*b1b.w;
        __sincosf(e0, &Ba2, &Ba1);
        __sincosf(e1, &Bb2, &Bb1);
        __sincosf(e2, &Bc2, &Bc1);
        __sincosf(e3, &Bd2, &Bd1);
    }
    __syncthreads();   // coefficients ready

    // ---- Patch eval for both images + shared-W partial GEMV ----
    float accA[10], accB[10];
    #pragma unroll
    for (int k = 0; k < 10; k++) { accA[k] = 0.f; accB[k] = 0.f; }

    if (t < 196) {
        float fAa[3] = {1.f, Aa1, Aa2};
        float fAb[3] = {1.f, Ab1, Ab2};
        float fAc[3] = {1.f, Ac1, Ac2};
        float fAd[3] = {1.f, Ad1, Ad2};
        float fBa[3] = {1.f, Ba1, Ba2};
        float fBb[3] = {1.f, Bb1, Bb2};
        float fBc[3] = {1.f, Bc1, Bc2};
        float fBd[3] = {1.f, Bd1, Bd2};

        float Am0 = 0.f, Am1 = 0.f, Am2 = 0.f, Am3 = 0.f;
        float Bm0 = 0.f, Bm1 = 0.f, Bm2 = 0.f, Bm3 = 0.f;
        int idx = 0;
        #pragma unroll
        for (int e0 = 0; e0 < 3; e0++) {
            #pragma unroll
            for (int e1 = 0; e1 < 3; e1++) {
                float2 kA = scA[idx];
                float2 kB = scB[idx];
                idx++;
                float pAA = fAa[e0] * fAb[e1];
                float pAB = fAc[e0] * fAd[e1];
                float pBA = fBa[e0] * fBb[e1];
                float pBB = fBc[e0] * fBd[e1];
                Am0 = fmaf(kA.x, pAA, Am0);
                Am1 = fmaf(kA.y, pAA, Am1);
                Am2 = fmaf(kB.x, pAB, Am2);
                Am3 = fmaf(kB.y, pAB, Am3);
                Bm0 = fmaf(kA.x, pBA, Bm0);
                Bm1 = fmaf(kA.y, pBA, Bm1);
                Bm2 = fmaf(kB.x, pBB, Bm2);
                Bm3 = fmaf(kB.y, pBB, Bm3);
            }
        }

        // shared W load: features [4t, 4t+4) of both images
        #pragma unroll
        for (int k = 0; k < 10; k++) {
            float4 w4 = __ldg((const float4*)(W + k * 784 + 4 * t));
            accA[k] = fmaf(Am0, w4.x, fmaf(Am1, w4.y, fmaf(Am2, w4.z, Am3 * w4.w)));
            accB[k] = fmaf(Bm0, w4.x, fmaf(Bm1, w4.y, fmaf(Bm2, w4.z, Bm3 * w4.w)));
        }
    }

    // ---- Dual block reduction ----
    #pragma unroll
    for (int k = 0; k < 10; k++) {
        float vA = accA[k], vB = accB[k];
        #pragma unroll
        for (int d = 16; d > 0; d >>= 1) {
            vA += __shfl_xor_sync(0xffffffffu, vA, d);
            vB += __shfl_xor_sync(0xffffffffu, vB, d);
        }
        accA[k] = vA; accB[k] = vB;
    }
    int lane = t & 31, wid = t >> 5;
    if (lane == 0) {
        #pragma unroll
        for (int k = 0; k < 10; k++) {
            wpart[0][wid][k] = accA[k];
            wpart[1][wid][k] = accB[k];
        }
    }
    __syncthreads();

    // ---- Final logits + dual log_softmax (warp 0 only) ----
    if (t < 32) {
        if (t < 20) {
            int im = t / 10, k = t % 10;
            float v = bvec[k];
            #pragma unroll
            for (int w = 0; w < 7; w++) v += wpart[im][w][k];
            slog[im][k] = v;
        }
        __syncwarp();
        if (t < 2) {
            float mx = slog[t][0];
            #pragma unroll
            for (int k = 1; k < 10; k++) mx = fmaxf(mx, slog[t][k]);
            float se = 0.f;
            #pragma unroll
            for (int k = 0; k < 10; k++) se += __expf(slog[t][k] - mx);
            slse[t] = mx + __logf(se);
        }
        __syncwarp();
        if (t < 20) {
            int im = t / 10, k = t % 10;
            out[(size_t)(2 * b + im) * 10 + k] = slog[im][k] - slse[im];
        }
    }
}

// ---------------------------------------------------------------------------

extern "C" void kernel_launch(void* const* d_in, const int* in_sizes, int n_in,
                              void* d_out, int out_size)
{
    const float* x     = (const float*)d_in[0];   // [2048,1,56,56]
    const float* cw    = (const float*)d_in[1];   // [1,1,2,2]
    const float* theta = (const float*)d_in[2];   // [6]
    const float* W     = (const float*)d_in[3];   // [10,784]
    const float* bvec  = (const float*)d_in[4];   // [10]
    float* out = (float*)d_out;                   // [2048,10]

    int B = in_sizes[0] / 3136;                   // 2048

    fused_kernel<<<B / 2, 224>>>(x, cw, theta, W, bvec, out);
}